// round 1
// baseline (speedup 1.0000x reference)
#include <cuda_runtime.h>
#include <cuda_bf16.h>

// Problem constants
#define D_MODEL 1024
#define N_HEADS 16
#define D_K     64
#define BATCH   2
#define SEQ     2048
#define M_ROWS  (BATCH * SEQ)   // 4096

// Scratch buffers (allocation-free rule: __device__ globals)
__device__ float g_Q[M_ROWS * D_MODEL];
__device__ float g_K[M_ROWS * D_MODEL];
__device__ float g_V[M_ROWS * D_MODEL];
__device__ float g_O[M_ROWS * D_MODEL];

// ---------------------------------------------------------------------------
// SGEMM: C[M,N] = A[M,K] @ W[K,N] + bias[N]
// BM=BN=128, BK=16, 256 threads, 8x8 per-thread register tile.
// ---------------------------------------------------------------------------
__global__ __launch_bounds__(256)
void gemm_bias_kernel(const float* __restrict__ A,
                      const float* __restrict__ W,
                      const float* __restrict__ bias,
                      float* __restrict__ C,
                      int M, int N, int K)
{
    __shared__ float Ast[16][132];  // A tile transposed: [kk][row], pad 4 (528B rows, 16B aligned)
    __shared__ float Bs [16][132];  // W tile: [kk][col]

    const int tid = threadIdx.x;
    const int tx  = tid & 15;       // 0..15  -> N direction
    const int ty  = tid >> 4;       // 0..15  -> M direction
    const int m0  = blockIdx.y * 128;
    const int n0  = blockIdx.x * 128;

    float acc[8][8];
    #pragma unroll
    for (int i = 0; i < 8; i++)
        #pragma unroll
        for (int j = 0; j < 8; j++) acc[i][j] = 0.f;

    for (int k0 = 0; k0 < K; k0 += 16) {
        // Load A tile (128 rows x 16 k) transposed into Ast. 512 float4 loads.
        #pragma unroll
        for (int t = tid; t < 512; t += 256) {
            int row = t >> 2;
            int kk  = (t & 3) * 4;
            float4 a = *(const float4*)&A[(size_t)(m0 + row) * K + k0 + kk];
            Ast[kk + 0][row] = a.x;
            Ast[kk + 1][row] = a.y;
            Ast[kk + 2][row] = a.z;
            Ast[kk + 3][row] = a.w;
        }
        // Load W tile (16 k x 128 cols). 512 float4 loads.
        #pragma unroll
        for (int t = tid; t < 512; t += 256) {
            int row = t >> 5;
            int col = (t & 31) * 4;
            *(float4*)&Bs[row][col] = *(const float4*)&W[(size_t)(k0 + row) * N + n0 + col];
        }
        __syncthreads();

        #pragma unroll
        for (int kk = 0; kk < 16; kk++) {
            float ra[8], rb[8];
            float4 a0 = *(const float4*)&Ast[kk][ty * 8];
            float4 a1 = *(const float4*)&Ast[kk][ty * 8 + 4];
            ra[0]=a0.x; ra[1]=a0.y; ra[2]=a0.z; ra[3]=a0.w;
            ra[4]=a1.x; ra[5]=a1.y; ra[6]=a1.z; ra[7]=a1.w;
            float4 b0 = *(const float4*)&Bs[kk][tx * 8];
            float4 b1 = *(const float4*)&Bs[kk][tx * 8 + 4];
            rb[0]=b0.x; rb[1]=b0.y; rb[2]=b0.z; rb[3]=b0.w;
            rb[4]=b1.x; rb[5]=b1.y; rb[6]=b1.z; rb[7]=b1.w;
            #pragma unroll
            for (int i = 0; i < 8; i++)
                #pragma unroll
                for (int j = 0; j < 8; j++)
                    acc[i][j] = fmaf(ra[i], rb[j], acc[i][j]);
        }
        __syncthreads();
    }

    #pragma unroll
    for (int i = 0; i < 8; i++) {
        int row = m0 + ty * 8 + i;
        #pragma unroll
        for (int j = 0; j < 8; j += 4) {
            int col = n0 + tx * 8 + j;
            float4 o;
            o.x = acc[i][j + 0] + bias[col + 0];
            o.y = acc[i][j + 1] + bias[col + 1];
            o.z = acc[i][j + 2] + bias[col + 2];
            o.w = acc[i][j + 3] + bias[col + 3];
            *(float4*)&C[(size_t)row * N + col] = o;
        }
    }
}

// ---------------------------------------------------------------------------
// Flash-attention tile kernel.
// One CTA = 64 query rows of one (batch, head). 256 threads, 16x16 layout,
// 4x4 S/O elements per thread. Online softmax. P tile reuses Ks storage.
// Dynamic smem: 3 * 64 * 65 * 4 = 49920 bytes.
// ---------------------------------------------------------------------------
__global__ __launch_bounds__(256)
void attn_kernel(const float* __restrict__ Q,
                 const float* __restrict__ K,
                 const float* __restrict__ V,
                 float* __restrict__ O)
{
    extern __shared__ float sm[];
    float (*Qs)[65] = (float(*)[65])sm;
    float (*Ks)[65] = (float(*)[65])(sm + 64 * 65);       // also reused for P
    float (*Vs)[65] = (float(*)[65])(sm + 2 * 64 * 65);

    const int tid = threadIdx.x;
    const int tx  = tid & 15;
    const int ty  = tid >> 4;
    const int q0  = blockIdx.x * 64;
    const int h   = blockIdx.y;
    const int b   = blockIdx.z;

    const float* Qb = Q + (size_t)(b * SEQ) * D_MODEL + h * D_K;
    const float* Kb = K + (size_t)(b * SEQ) * D_MODEL + h * D_K;
    const float* Vb = V + (size_t)(b * SEQ) * D_MODEL + h * D_K;

    // Load Q tile (64 x 64)
    #pragma unroll
    for (int t = tid; t < 64 * 64; t += 256) {
        int r = t >> 6, c = t & 63;
        Qs[r][c] = Qb[(size_t)(q0 + r) * D_MODEL + c];
    }

    float m_i[4], l_i[4], o[4][4];
    #pragma unroll
    for (int i = 0; i < 4; i++) {
        m_i[i] = -1e30f; l_i[i] = 0.f;
        #pragma unroll
        for (int j = 0; j < 4; j++) o[i][j] = 0.f;
    }

    for (int kt = 0; kt < SEQ; kt += 64) {
        __syncthreads();   // previous iteration's P/V readers done
        #pragma unroll
        for (int t = tid; t < 64 * 64; t += 256) {
            int r = t >> 6, c = t & 63;
            Ks[r][c] = Kb[(size_t)(kt + r) * D_MODEL + c];
            Vs[r][c] = Vb[(size_t)(kt + r) * D_MODEL + c];
        }
        __syncthreads();

        // S = (Q @ K^T) * 1/sqrt(d_k)
        float s[4][4];
        #pragma unroll
        for (int i = 0; i < 4; i++)
            #pragma unroll
            for (int j = 0; j < 4; j++) s[i][j] = 0.f;

        #pragma unroll 4
        for (int k = 0; k < 64; k++) {
            float rq[4], rk[4];
            #pragma unroll
            for (int i = 0; i < 4; i++) rq[i] = Qs[ty * 4 + i][k];
            #pragma unroll
            for (int j = 0; j < 4; j++) rk[j] = Ks[tx * 4 + j][k];
            #pragma unroll
            for (int i = 0; i < 4; i++)
                #pragma unroll
                for (int j = 0; j < 4; j++)
                    s[i][j] = fmaf(rq[i], rk[j], s[i][j]);
        }

        const float scale = 0.125f;   // 1/sqrt(64)
        #pragma unroll
        for (int i = 0; i < 4; i++) {
            #pragma unroll
            for (int j = 0; j < 4; j++) s[i][j] *= scale;

            float mx = fmaxf(fmaxf(s[i][0], s[i][1]), fmaxf(s[i][2], s[i][3]));
            #pragma unroll
            for (int off = 1; off < 16; off <<= 1)
                mx = fmaxf(mx, __shfl_xor_sync(0xffffffffu, mx, off));

            float mnew = fmaxf(m_i[i], mx);
            float corr = __expf(m_i[i] - mnew);
            float rs = 0.f;
            #pragma unroll
            for (int j = 0; j < 4; j++) {
                s[i][j] = __expf(s[i][j] - mnew);
                rs += s[i][j];
            }
            #pragma unroll
            for (int off = 1; off < 16; off <<= 1)
                rs += __shfl_xor_sync(0xffffffffu, rs, off);

            l_i[i] = l_i[i] * corr + rs;
            m_i[i] = mnew;
            #pragma unroll
            for (int j = 0; j < 4; j++) o[i][j] *= corr;
        }

        __syncthreads();   // all S reads of Ks done before overwrite with P
        #pragma unroll
        for (int i = 0; i < 4; i++)
            #pragma unroll
            for (int j = 0; j < 4; j++)
                Ks[ty * 4 + i][tx * 4 + j] = s[i][j];
        __syncthreads();

        // O += P @ V
        #pragma unroll 4
        for (int k = 0; k < 64; k++) {
            float rp[4], rv[4];
            #pragma unroll
            for (int i = 0; i < 4; i++) rp[i] = Ks[ty * 4 + i][k];
            #pragma unroll
            for (int j = 0; j < 4; j++) rv[j] = Vs[k][tx * 4 + j];
            #pragma unroll
            for (int i = 0; i < 4; i++)
                #pragma unroll
                for (int j = 0; j < 4; j++)
                    o[i][j] = fmaf(rp[i], rv[j], o[i][j]);
        }
    }

    // Epilogue: normalize and write in (B, L, D) layout
    float* Ob = O + (size_t)(b * SEQ) * D_MODEL + h * D_K;
    #pragma unroll
    for (int i = 0; i < 4; i++) {
        float inv_l = 1.0f / l_i[i];
        #pragma unroll
        for (int j = 0; j < 4; j++)
            Ob[(size_t)(q0 + ty * 4 + i) * D_MODEL + tx * 4 + j] = o[i][j] * inv_l;
    }
}

// ---------------------------------------------------------------------------
// kernel_launch
// Inputs (metadata order): q, k, v, w_q, b_q, w_k, b_k, w_v, b_v, w_o, b_o
// ---------------------------------------------------------------------------
extern "C" void kernel_launch(void* const* d_in, const int* in_sizes, int n_in,
                              void* d_out, int out_size)
{
    const float* q   = (const float*)d_in[0];
    const float* k   = (const float*)d_in[1];
    const float* v   = (const float*)d_in[2];
    const float* w_q = (const float*)d_in[3];
    const float* b_q = (const float*)d_in[4];
    const float* w_k = (const float*)d_in[5];
    const float* b_k = (const float*)d_in[6];
    const float* w_v = (const float*)d_in[7];
    const float* b_v = (const float*)d_in[8];
    const float* w_o = (const float*)d_in[9];
    const float* b_o = (const float*)d_in[10];
    float* out = (float*)d_out;

    float *gq, *gk, *gv, *go;
    cudaGetSymbolAddress((void**)&gq, g_Q);
    cudaGetSymbolAddress((void**)&gk, g_K);
    cudaGetSymbolAddress((void**)&gv, g_V);
    cudaGetSymbolAddress((void**)&go, g_O);

    const int attn_smem = 3 * 64 * 65 * 4;  // 49920 bytes
    cudaFuncSetAttribute(attn_kernel, cudaFuncAttributeMaxDynamicSharedMemorySize, attn_smem);

    dim3 gemm_grid(D_MODEL / 128, M_ROWS / 128);  // (8, 32)
    gemm_bias_kernel<<<gemm_grid, 256>>>(q, w_q, b_q, gq, M_ROWS, D_MODEL, D_MODEL);
    gemm_bias_kernel<<<gemm_grid, 256>>>(k, w_k, b_k, gk, M_ROWS, D_MODEL, D_MODEL);
    gemm_bias_kernel<<<gemm_grid, 256>>>(v, w_v, b_v, gv, M_ROWS, D_MODEL, D_MODEL);

    dim3 attn_grid(SEQ / 64, N_HEADS, BATCH);     // (32, 16, 2)
    attn_kernel<<<attn_grid, 256, attn_smem>>>(gq, gk, gv, go);

    gemm_bias_kernel<<<gemm_grid, 256>>>(go, w_o, b_o, out, M_ROWS, D_MODEL, D_MODEL);
}

// round 2
// speedup vs baseline: 3.0866x; 3.0866x over previous
#include <cuda_runtime.h>
#include <cstdint>

#define D_MODEL 1024
#define N_HEADS 16
#define D_K     64
#define BATCH   2
#define SEQ     2048
#define M_ROWS  (BATCH * SEQ)   // 4096

// Scratch (allocation-free rule: __device__ globals)
__device__ float g_Q[M_ROWS * D_MODEL];
__device__ float g_K[M_ROWS * D_MODEL];
__device__ float g_V[M_ROWS * D_MODEL];
__device__ float g_O[M_ROWS * D_MODEL];

__device__ __forceinline__ uint32_t f2tf32(float x) {
    uint32_t r;
    asm("cvt.rna.tf32.f32 %0, %1;" : "=r"(r) : "f"(x));
    return r;
}

__device__ __forceinline__ void mma_tf32(float c[4],
                                         uint32_t a0, uint32_t a1, uint32_t a2, uint32_t a3,
                                         uint32_t b0, uint32_t b1) {
    asm volatile(
        "mma.sync.aligned.m16n8k8.row.col.f32.tf32.tf32.f32 "
        "{%0,%1,%2,%3}, {%4,%5,%6,%7}, {%8,%9}, {%0,%1,%2,%3};"
        : "+f"(c[0]), "+f"(c[1]), "+f"(c[2]), "+f"(c[3])
        : "r"(a0), "r"(a1), "r"(a2), "r"(a3), "r"(b0), "r"(b1));
}

// ---------------------------------------------------------------------------
// TF32 GEMM: C[M,N] = A[M,K] @ W[K,N] + bias
// 256 threads, BM=BN=128, BK=16. Warp grid 2(M)x4(N); warp tile 64x32.
// ---------------------------------------------------------------------------
__global__ __launch_bounds__(256)
void gemm_tf32(const float* __restrict__ A,
               const float* __restrict__ W,
               const float* __restrict__ bias,
               float* __restrict__ C,
               int M, int N, int K)
{
    __shared__ uint32_t As[128][20];   // [row][k], pitch 20 -> frag loads conflict-free
    __shared__ uint32_t Bs[16][136];   // [k][col], pitch 136 -> frag loads conflict-free

    const int tid  = threadIdx.x;
    const int lane = tid & 31;
    const int wid  = tid >> 5;
    const int gid  = lane >> 2;
    const int tg   = lane & 3;
    const int warp_m = wid & 1;    // 0..1
    const int warp_n = wid >> 1;   // 0..3
    const int m0 = blockIdx.y * 128;
    const int n0 = blockIdx.x * 128;

    float c[4][4][4];
    #pragma unroll
    for (int mt = 0; mt < 4; mt++)
        #pragma unroll
        for (int nt = 0; nt < 4; nt++)
            #pragma unroll
            for (int i = 0; i < 4; i++) c[mt][nt][i] = 0.f;

    for (int k0 = 0; k0 < K; k0 += 16) {
        __syncthreads();
        // A tile: 128 rows x 16 k = 512 float4
        #pragma unroll
        for (int t = tid; t < 512; t += 256) {
            int row = t >> 2, kk = (t & 3) * 4;
            float4 a = *(const float4*)&A[(size_t)(m0 + row) * K + k0 + kk];
            uint4 u = { f2tf32(a.x), f2tf32(a.y), f2tf32(a.z), f2tf32(a.w) };
            *(uint4*)&As[row][kk] = u;
        }
        // W tile: 16 k x 128 cols = 512 float4
        #pragma unroll
        for (int t = tid; t < 512; t += 256) {
            int row = t >> 5, col = (t & 31) * 4;
            float4 b = *(const float4*)&W[(size_t)(k0 + row) * N + n0 + col];
            uint4 u = { f2tf32(b.x), f2tf32(b.y), f2tf32(b.z), f2tf32(b.w) };
            *(uint4*)&Bs[row][col] = u;
        }
        __syncthreads();

        #pragma unroll
        for (int ks = 0; ks < 16; ks += 8) {
            uint32_t af[4][4], bf[4][2];
            #pragma unroll
            for (int mt = 0; mt < 4; mt++) {
                int r = warp_m * 64 + mt * 16;
                af[mt][0] = As[r + gid    ][ks + tg];
                af[mt][1] = As[r + gid + 8][ks + tg];
                af[mt][2] = As[r + gid    ][ks + tg + 4];
                af[mt][3] = As[r + gid + 8][ks + tg + 4];
            }
            #pragma unroll
            for (int nt = 0; nt < 4; nt++) {
                int cb = warp_n * 32 + nt * 8;
                bf[nt][0] = Bs[ks + tg    ][cb + gid];
                bf[nt][1] = Bs[ks + tg + 4][cb + gid];
            }
            #pragma unroll
            for (int mt = 0; mt < 4; mt++)
                #pragma unroll
                for (int nt = 0; nt < 4; nt++)
                    mma_tf32(c[mt][nt], af[mt][0], af[mt][1], af[mt][2], af[mt][3],
                             bf[nt][0], bf[nt][1]);
        }
    }

    // Epilogue: C frag rows (gid, gid+8), cols tg*2..+1 per 16x8 tile
    #pragma unroll
    for (int mt = 0; mt < 4; mt++) {
        int r0 = m0 + warp_m * 64 + mt * 16 + gid;
        #pragma unroll
        for (int nt = 0; nt < 4; nt++) {
            int col = n0 + warp_n * 32 + nt * 8 + tg * 2;
            float2 bb = *(const float2*)&bias[col];
            float2 o0 = { c[mt][nt][0] + bb.x, c[mt][nt][1] + bb.y };
            *(float2*)&C[(size_t)r0 * N + col] = o0;
            float2 o1 = { c[mt][nt][2] + bb.x, c[mt][nt][3] + bb.y };
            *(float2*)&C[(size_t)(r0 + 8) * N + col] = o1;
        }
    }
}

// ---------------------------------------------------------------------------
// TF32 flash attention. CTA = 128 query rows x one (b,h). 8 warps x 16 rows.
// Key tile 64. Dynamic smem: Qs[128][68] Ks[64][68] Vs[64][72] Ps[128][68]
// (uint32 tf32) = 105472 bytes.
// ---------------------------------------------------------------------------
#define QS_P 68
#define KS_P 68
#define VS_P 72
#define PS_P 68
#define ATTN_SMEM ((128*QS_P + 64*KS_P + 64*VS_P + 128*PS_P) * 4)

__global__ __launch_bounds__(256)
void attn_tf32(const float* __restrict__ Q,
               const float* __restrict__ K,
               const float* __restrict__ V,
               float* __restrict__ O)
{
    extern __shared__ uint32_t sm[];
    uint32_t* Qs = sm;
    uint32_t* Ks = Qs + 128 * QS_P;
    uint32_t* Vs = Ks + 64 * KS_P;
    uint32_t* Ps = Vs + 64 * VS_P;

    const int tid  = threadIdx.x;
    const int lane = tid & 31;
    const int wid  = tid >> 5;
    const int gid  = lane >> 2;
    const int tg   = lane & 3;
    const int row_base = wid * 16;

    const int q0 = blockIdx.x * 128;
    const int h  = blockIdx.y;
    const int b  = blockIdx.z;

    const float* Qb = Q + (size_t)b * SEQ * D_MODEL + h * D_K;
    const float* Kb = K + (size_t)b * SEQ * D_MODEL + h * D_K;
    const float* Vb = V + (size_t)b * SEQ * D_MODEL + h * D_K;

    // Load Q tile 128x64, scale by 1/sqrt(64), convert to tf32
    #pragma unroll
    for (int t = tid; t < 2048; t += 256) {
        int r = t >> 4, cc = (t & 15) * 4;
        float4 q = *(const float4*)&Qb[(size_t)(q0 + r) * D_MODEL + cc];
        uint4 u = { f2tf32(q.x * 0.125f), f2tf32(q.y * 0.125f),
                    f2tf32(q.z * 0.125f), f2tf32(q.w * 0.125f) };
        *(uint4*)&Qs[r * QS_P + cc] = u;
    }

    float o[8][4];
    #pragma unroll
    for (int nt = 0; nt < 8; nt++)
        #pragma unroll
        for (int i = 0; i < 4; i++) o[nt][i] = 0.f;
    float m_i[2] = { -1e30f, -1e30f };
    float l_i[2] = { 0.f, 0.f };

    for (int kt = 0; kt < SEQ; kt += 64) {
        __syncthreads();  // prior-iter Ks/Vs readers done; also covers Qs on iter 0
        #pragma unroll
        for (int t = tid; t < 1024; t += 256) {
            int r = t >> 4, cc = (t & 15) * 4;
            float4 kk = *(const float4*)&Kb[(size_t)(kt + r) * D_MODEL + cc];
            uint4 uk = { f2tf32(kk.x), f2tf32(kk.y), f2tf32(kk.z), f2tf32(kk.w) };
            *(uint4*)&Ks[r * KS_P + cc] = uk;
            float4 vv = *(const float4*)&Vb[(size_t)(kt + r) * D_MODEL + cc];
            uint4 uv = { f2tf32(vv.x), f2tf32(vv.y), f2tf32(vv.z), f2tf32(vv.w) };
            *(uint4*)&Vs[r * VS_P + cc] = uv;
        }
        __syncthreads();

        // S = Qs @ Ks^T  (warp: 16 x 64, 8 n-tiles, 8 k-steps)
        float s[8][4];
        #pragma unroll
        for (int nt = 0; nt < 8; nt++)
            #pragma unroll
            for (int i = 0; i < 4; i++) s[nt][i] = 0.f;

        #pragma unroll
        for (int ks = 0; ks < 64; ks += 8) {
            uint32_t a0 = Qs[(row_base + gid    ) * QS_P + ks + tg];
            uint32_t a1 = Qs[(row_base + gid + 8) * QS_P + ks + tg];
            uint32_t a2 = Qs[(row_base + gid    ) * QS_P + ks + tg + 4];
            uint32_t a3 = Qs[(row_base + gid + 8) * QS_P + ks + tg + 4];
            #pragma unroll
            for (int nt = 0; nt < 8; nt++) {
                uint32_t b0 = Ks[(nt * 8 + gid) * KS_P + ks + tg];
                uint32_t b1 = Ks[(nt * 8 + gid) * KS_P + ks + tg + 4];
                mma_tf32(s[nt], a0, a1, a2, a3, b0, b1);
            }
        }

        // Online softmax: thread holds rows (row_base+gid) and (+8);
        // row r cols = nt*8 + tg*2 (+1). Reduce across the lane quad.
        #pragma unroll
        for (int half = 0; half < 2; half++) {
            float mx = -1e30f;
            #pragma unroll
            for (int nt = 0; nt < 8; nt++)
                mx = fmaxf(mx, fmaxf(s[nt][half * 2], s[nt][half * 2 + 1]));
            mx = fmaxf(mx, __shfl_xor_sync(0xffffffffu, mx, 1));
            mx = fmaxf(mx, __shfl_xor_sync(0xffffffffu, mx, 2));

            float mnew = fmaxf(m_i[half], mx);
            float corr = __expf(m_i[half] - mnew);
            float rs = 0.f;
            #pragma unroll
            for (int nt = 0; nt < 8; nt++) {
                s[nt][half * 2]     = __expf(s[nt][half * 2]     - mnew);
                s[nt][half * 2 + 1] = __expf(s[nt][half * 2 + 1] - mnew);
                rs += s[nt][half * 2] + s[nt][half * 2 + 1];
            }
            rs += __shfl_xor_sync(0xffffffffu, rs, 1);
            rs += __shfl_xor_sync(0xffffffffu, rs, 2);

            l_i[half] = l_i[half] * corr + rs;
            m_i[half] = mnew;
            #pragma unroll
            for (int nt = 0; nt < 8; nt++) {
                o[nt][half * 2]     *= corr;
                o[nt][half * 2 + 1] *= corr;
            }
        }

        // P -> smem (tf32); each warp owns its 16 rows of Ps
        __syncwarp();
        #pragma unroll
        for (int nt = 0; nt < 8; nt++) {
            int cc = nt * 8 + tg * 2;
            Ps[(row_base + gid    ) * PS_P + cc    ] = f2tf32(s[nt][0]);
            Ps[(row_base + gid    ) * PS_P + cc + 1] = f2tf32(s[nt][1]);
            Ps[(row_base + gid + 8) * PS_P + cc    ] = f2tf32(s[nt][2]);
            Ps[(row_base + gid + 8) * PS_P + cc + 1] = f2tf32(s[nt][3]);
        }
        __syncwarp();

        // O += P @ V (k = 64 keys, 8 k-steps)
        #pragma unroll
        for (int ks = 0; ks < 64; ks += 8) {
            uint32_t a0 = Ps[(row_base + gid    ) * PS_P + ks + tg];
            uint32_t a1 = Ps[(row_base + gid + 8) * PS_P + ks + tg];
            uint32_t a2 = Ps[(row_base + gid    ) * PS_P + ks + tg + 4];
            uint32_t a3 = Ps[(row_base + gid + 8) * PS_P + ks + tg + 4];
            #pragma unroll
            for (int nt = 0; nt < 8; nt++) {
                uint32_t b0 = Vs[(ks + tg    ) * VS_P + nt * 8 + gid];
                uint32_t b1 = Vs[(ks + tg + 4) * VS_P + nt * 8 + gid];
                mma_tf32(o[nt], a0, a1, a2, a3, b0, b1);
            }
        }
    }

    // Epilogue: normalize, write (B, L, D) layout
    float inv0 = 1.0f / l_i[0];
    float inv1 = 1.0f / l_i[1];
    float* Ob = g_O + (size_t)b * SEQ * D_MODEL + h * D_K;
    int r0 = q0 + row_base + gid;
    #pragma unroll
    for (int nt = 0; nt < 8; nt++) {
        int col = nt * 8 + tg * 2;
        float2 t0 = { o[nt][0] * inv0, o[nt][1] * inv0 };
        *(float2*)&Ob[(size_t)r0 * D_MODEL + col] = t0;
        float2 t1 = { o[nt][2] * inv1, o[nt][3] * inv1 };
        *(float2*)&Ob[(size_t)(r0 + 8) * D_MODEL + col] = t1;
    }
    (void)O;
}

// ---------------------------------------------------------------------------
// kernel_launch — inputs: q, k, v, w_q, b_q, w_k, b_k, w_v, b_v, w_o, b_o
// ---------------------------------------------------------------------------
extern "C" void kernel_launch(void* const* d_in, const int* in_sizes, int n_in,
                              void* d_out, int out_size)
{
    const float* q   = (const float*)d_in[0];
    const float* k   = (const float*)d_in[1];
    const float* v   = (const float*)d_in[2];
    const float* w_q = (const float*)d_in[3];
    const float* b_q = (const float*)d_in[4];
    const float* w_k = (const float*)d_in[5];
    const float* b_k = (const float*)d_in[6];
    const float* w_v = (const float*)d_in[7];
    const float* b_v = (const float*)d_in[8];
    const float* w_o = (const float*)d_in[9];
    const float* b_o = (const float*)d_in[10];
    float* out = (float*)d_out;

    float *gq, *gk, *gv, *go;
    cudaGetSymbolAddress((void**)&gq, g_Q);
    cudaGetSymbolAddress((void**)&gk, g_K);
    cudaGetSymbolAddress((void**)&gv, g_V);
    cudaGetSymbolAddress((void**)&go, g_O);

    cudaFuncSetAttribute(attn_tf32, cudaFuncAttributeMaxDynamicSharedMemorySize, ATTN_SMEM);

    dim3 gemm_grid(D_MODEL / 128, M_ROWS / 128);  // (8, 32)
    gemm_tf32<<<gemm_grid, 256>>>(q, w_q, b_q, gq, M_ROWS, D_MODEL, D_MODEL);
    gemm_tf32<<<gemm_grid, 256>>>(k, w_k, b_k, gk, M_ROWS, D_MODEL, D_MODEL);
    gemm_tf32<<<gemm_grid, 256>>>(v, w_v, b_v, gv, M_ROWS, D_MODEL, D_MODEL);

    dim3 attn_grid(SEQ / 128, N_HEADS, BATCH);    // (16, 16, 2)
    attn_tf32<<<attn_grid, 256, ATTN_SMEM>>>(gq, gk, gv, go);

    gemm_tf32<<<gemm_grid, 256>>>(go, w_o, b_o, out, M_ROWS, D_MODEL, D_MODEL);
}

// round 3
// speedup vs baseline: 3.2960x; 1.0679x over previous
#include <cuda_runtime.h>
#include <cstdint>

#define D_MODEL 1024
#define N_HEADS 16
#define D_K     64
#define BATCH   2
#define SEQ     2048
#define M_ROWS  (BATCH * SEQ)   // 4096

// Scratch (allocation-free rule: __device__ globals)
__device__ float g_Q[M_ROWS * D_MODEL];
__device__ float g_K[M_ROWS * D_MODEL];
__device__ float g_V[M_ROWS * D_MODEL];
__device__ float g_O[M_ROWS * D_MODEL];

__device__ __forceinline__ uint32_t f2tf32(float x) {
    uint32_t r;
    asm("cvt.rna.tf32.f32 %0, %1;" : "=r"(r) : "f"(x));
    return r;
}

__device__ __forceinline__ void mma_tf32(float c[4],
                                         uint32_t a0, uint32_t a1, uint32_t a2, uint32_t a3,
                                         uint32_t b0, uint32_t b1) {
    asm volatile(
        "mma.sync.aligned.m16n8k8.row.col.f32.tf32.tf32.f32 "
        "{%0,%1,%2,%3}, {%4,%5,%6,%7}, {%8,%9}, {%0,%1,%2,%3};"
        : "+f"(c[0]), "+f"(c[1]), "+f"(c[2]), "+f"(c[3])
        : "r"(a0), "r"(a1), "r"(a2), "r"(a3), "r"(b0), "r"(b1));
}

__device__ __forceinline__ uint32_t smem_u32(const void* p) {
    return (uint32_t)__cvta_generic_to_shared(p);
}
__device__ __forceinline__ void cpasync16(uint32_t dst, const void* src) {
    asm volatile("cp.async.cg.shared.global [%0], [%1], 16;" :: "r"(dst), "l"(src));
}
__device__ __forceinline__ void cpasync_commit() {
    asm volatile("cp.async.commit_group;");
}
__device__ __forceinline__ void cpasync_wait_all() {
    asm volatile("cp.async.wait_group 0;");
}

// ---------------------------------------------------------------------------
// TF32 GEMM: C[4096,1024] = A @ W + bias. BM=BN=128, BK=32, 2-stage cp.async.
// 256 threads; warp grid 2(M)x4(N); warp tile 64x32.
// Raw fp32 in smem; cvt.rna.tf32 at fragment load.
// Dynamic smem: 2*(128*36 + 32*136)*4 = 71680 B.
// ---------------------------------------------------------------------------
#define GA_P 36
#define GB_P 136
#define GEMM_STAGE_A (128 * GA_P)
#define GEMM_STAGE_B (32 * GB_P)
#define GEMM_SMEM ((2 * (GEMM_STAGE_A + GEMM_STAGE_B)) * 4)

__global__ __launch_bounds__(256)
void gemm_tf32(const float* __restrict__ A,
               const float* __restrict__ W,
               const float* __restrict__ bias,
               float* __restrict__ C)
{
    extern __shared__ float sg[];
    float* Asm = sg;                        // [2][128][GA_P]
    float* Bsm = sg + 2 * GEMM_STAGE_A;     // [2][32][GB_P]

    const int tid  = threadIdx.x;
    const int lane = tid & 31;
    const int wid  = tid >> 5;
    const int gid  = lane >> 2;
    const int tg   = lane & 3;
    const int warp_m = wid & 1;
    const int warp_n = wid >> 1;
    const int m0 = blockIdx.y * 128;
    const int n0 = blockIdx.x * 128;

    // cp.async thread mapping (4 x 16B for A, 4 x 16B for B per stage)
    const int a_row = tid >> 1;             // 0..127   (2 float4 per row per k0..) -> idx scheme below
    // A tile: 128 rows x 32 k = 1024 float4 ; idx = tid + i*256 : row=idx>>3, kk=(idx&7)*4
    // B tile: 32 k x 128 col = 1024 float4 ; idx = tid + i*256 : k=idx>>5, col=(idx&31)*4

    float c[4][4][4];
    #pragma unroll
    for (int mt = 0; mt < 4; mt++)
        #pragma unroll
        for (int nt = 0; nt < 4; nt++)
            #pragma unroll
            for (int i = 0; i < 4; i++) c[mt][nt][i] = 0.f;

    // Prologue: stage 0
    {
        #pragma unroll
        for (int i = 0; i < 4; i++) {
            int idx = tid + i * 256;
            int row = idx >> 3, kk = (idx & 7) * 4;
            cpasync16(smem_u32(&Asm[row * GA_P + kk]),
                      &A[(size_t)(m0 + row) * D_MODEL + kk]);
        }
        #pragma unroll
        for (int i = 0; i < 4; i++) {
            int idx = tid + i * 256;
            int kk = idx >> 5, col = (idx & 31) * 4;
            cpasync16(smem_u32(&Bsm[kk * GB_P + col]),
                      &W[(size_t)kk * D_MODEL + n0 + col]);
        }
        cpasync_commit();
    }

    int st = 0;
    for (int k0 = 0; k0 < D_MODEL; k0 += 32) {
        cpasync_wait_all();
        __syncthreads();

        if (k0 + 32 < D_MODEL) {
            float* Ad = Asm + (st ^ 1) * GEMM_STAGE_A;
            float* Bd = Bsm + (st ^ 1) * GEMM_STAGE_B;
            #pragma unroll
            for (int i = 0; i < 4; i++) {
                int idx = tid + i * 256;
                int row = idx >> 3, kk = (idx & 7) * 4;
                cpasync16(smem_u32(&Ad[row * GA_P + kk]),
                          &A[(size_t)(m0 + row) * D_MODEL + k0 + 32 + kk]);
            }
            #pragma unroll
            for (int i = 0; i < 4; i++) {
                int idx = tid + i * 256;
                int kk = idx >> 5, col = (idx & 31) * 4;
                cpasync16(smem_u32(&Bd[kk * GB_P + col]),
                          &W[(size_t)(k0 + 32 + kk) * D_MODEL + n0 + col]);
            }
            cpasync_commit();
        }

        const float* As = Asm + st * GEMM_STAGE_A;
        const float* Bq = Bsm + st * GEMM_STAGE_B;

        #pragma unroll
        for (int ks = 0; ks < 32; ks += 8) {
            uint32_t af[4][4], bf[4][2];
            #pragma unroll
            for (int mt = 0; mt < 4; mt++) {
                int r = warp_m * 64 + mt * 16;
                af[mt][0] = f2tf32(As[(r + gid    ) * GA_P + ks + tg]);
                af[mt][1] = f2tf32(As[(r + gid + 8) * GA_P + ks + tg]);
                af[mt][2] = f2tf32(As[(r + gid    ) * GA_P + ks + tg + 4]);
                af[mt][3] = f2tf32(As[(r + gid + 8) * GA_P + ks + tg + 4]);
            }
            #pragma unroll
            for (int nt = 0; nt < 4; nt++) {
                int cb = warp_n * 32 + nt * 8;
                bf[nt][0] = f2tf32(Bq[(ks + tg    ) * GB_P + cb + gid]);
                bf[nt][1] = f2tf32(Bq[(ks + tg + 4) * GB_P + cb + gid]);
            }
            #pragma unroll
            for (int mt = 0; mt < 4; mt++)
                #pragma unroll
                for (int nt = 0; nt < 4; nt++)
                    mma_tf32(c[mt][nt], af[mt][0], af[mt][1], af[mt][2], af[mt][3],
                             bf[nt][0], bf[nt][1]);
        }
        st ^= 1;
    }

    #pragma unroll
    for (int mt = 0; mt < 4; mt++) {
        int r0 = m0 + warp_m * 64 + mt * 16 + gid;
        #pragma unroll
        for (int nt = 0; nt < 4; nt++) {
            int col = n0 + warp_n * 32 + nt * 8 + tg * 2;
            float2 bb = *(const float2*)&bias[col];
            float2 o0 = { c[mt][nt][0] + bb.x, c[mt][nt][1] + bb.y };
            *(float2*)&C[(size_t)r0 * D_MODEL + col] = o0;
            float2 o1 = { c[mt][nt][2] + bb.x, c[mt][nt][3] + bb.y };
            *(float2*)&C[(size_t)(r0 + 8) * D_MODEL + col] = o1;
        }
    }
}

// ---------------------------------------------------------------------------
// TF32 flash attention. CTA = 128 q rows x one (b,h). 8 warps x 16 rows.
// Q in registers (mma fragments). K/V: 2-stage cp.async (raw fp32, cvt at
// frag load). P via smem (tf32).
// Dynamic smem: 2*64*68 + 2*64*72 + 128*68 floats = 106496 B.
// ---------------------------------------------------------------------------
#define KS_P 68
#define VS_P 72
#define PS_P 68
#define K_STAGE (64 * KS_P)
#define V_STAGE (64 * VS_P)
#define ATTN_SMEM ((2 * K_STAGE + 2 * V_STAGE + 128 * PS_P) * 4)

__global__ __launch_bounds__(256)
void attn_tf32(const float* __restrict__ Q,
               const float* __restrict__ K,
               const float* __restrict__ V,
               float* __restrict__ O)
{
    extern __shared__ float sa[];
    float*    Kbuf = sa;                        // [2][64][KS_P] raw fp32
    float*    Vbuf = sa + 2 * K_STAGE;          // [2][64][VS_P] raw fp32
    uint32_t* Ps   = (uint32_t*)(sa + 2 * K_STAGE + 2 * V_STAGE);  // [128][PS_P] tf32

    const int tid  = threadIdx.x;
    const int lane = tid & 31;
    const int wid  = tid >> 5;
    const int gid  = lane >> 2;
    const int tg   = lane & 3;
    const int row_base = wid * 16;

    const int q0 = blockIdx.x * 128;
    const int h  = blockIdx.y;
    const int b  = blockIdx.z;

    const float* Qb = Q + (size_t)b * SEQ * D_MODEL + h * D_K;
    const float* Kb = K + (size_t)b * SEQ * D_MODEL + h * D_K;
    const float* Vb = V + (size_t)b * SEQ * D_MODEL + h * D_K;

    // Q tile (this warp's 16 rows) -> registers as mma A fragments, pre-scaled
    uint32_t qf[8][4];
    {
        const float* qr0 = Qb + (size_t)(q0 + row_base + gid) * D_MODEL;
        const float* qr1 = qr0 + (size_t)8 * D_MODEL;
        #pragma unroll
        for (int c8 = 0; c8 < 8; c8++) {
            qf[c8][0] = f2tf32(qr0[c8 * 8 + tg    ] * 0.125f);
            qf[c8][1] = f2tf32(qr1[c8 * 8 + tg    ] * 0.125f);
            qf[c8][2] = f2tf32(qr0[c8 * 8 + tg + 4] * 0.125f);
            qf[c8][3] = f2tf32(qr1[c8 * 8 + tg + 4] * 0.125f);
        }
    }

    // Prologue: stage 0 K/V (64 rows x 16 float4 each = 1024 float4; 4/thread each)
    #pragma unroll
    for (int i = 0; i < 4; i++) {
        int idx = tid + i * 256;
        int r = idx >> 4, c4 = (idx & 15) * 4;
        cpasync16(smem_u32(&Kbuf[r * KS_P + c4]), &Kb[(size_t)r * D_MODEL + c4]);
        cpasync16(smem_u32(&Vbuf[r * VS_P + c4]), &Vb[(size_t)r * D_MODEL + c4]);
    }
    cpasync_commit();

    float o[8][4];
    #pragma unroll
    for (int nt = 0; nt < 8; nt++)
        #pragma unroll
        for (int i = 0; i < 4; i++) o[nt][i] = 0.f;
    float m_i[2] = { -1e30f, -1e30f };
    float l_i[2] = { 0.f, 0.f };

    int st = 0;
    for (int kt = 0; kt < SEQ; kt += 64) {
        cpasync_wait_all();
        __syncthreads();

        if (kt + 64 < SEQ) {
            float* Kd = Kbuf + (st ^ 1) * K_STAGE;
            float* Vd = Vbuf + (st ^ 1) * V_STAGE;
            #pragma unroll
            for (int i = 0; i < 4; i++) {
                int idx = tid + i * 256;
                int r = idx >> 4, c4 = (idx & 15) * 4;
                cpasync16(smem_u32(&Kd[r * KS_P + c4]),
                          &Kb[(size_t)(kt + 64 + r) * D_MODEL + c4]);
                cpasync16(smem_u32(&Vd[r * VS_P + c4]),
                          &Vb[(size_t)(kt + 64 + r) * D_MODEL + c4]);
            }
            cpasync_commit();
        }

        const float* Ks = Kbuf + st * K_STAGE;
        const float* Vs = Vbuf + st * V_STAGE;

        // S = (Q/sqrt(dk)) @ K^T : warp 16 x 64
        float s[8][4];
        #pragma unroll
        for (int nt = 0; nt < 8; nt++)
            #pragma unroll
            for (int i = 0; i < 4; i++) s[nt][i] = 0.f;

        #pragma unroll
        for (int c8 = 0; c8 < 8; c8++) {
            int ks = c8 * 8;
            #pragma unroll
            for (int nt = 0; nt < 8; nt++) {
                uint32_t b0 = f2tf32(Ks[(nt * 8 + gid) * KS_P + ks + tg]);
                uint32_t b1 = f2tf32(Ks[(nt * 8 + gid) * KS_P + ks + tg + 4]);
                mma_tf32(s[nt], qf[c8][0], qf[c8][1], qf[c8][2], qf[c8][3], b0, b1);
            }
        }

        // Online softmax (rows row_base+gid, row_base+gid+8; quad reduce)
        #pragma unroll
        for (int half = 0; half < 2; half++) {
            float mx = -1e30f;
            #pragma unroll
            for (int nt = 0; nt < 8; nt++)
                mx = fmaxf(mx, fmaxf(s[nt][half * 2], s[nt][half * 2 + 1]));
            mx = fmaxf(mx, __shfl_xor_sync(0xffffffffu, mx, 1));
            mx = fmaxf(mx, __shfl_xor_sync(0xffffffffu, mx, 2));

            float mnew = fmaxf(m_i[half], mx);
            float corr = __expf(m_i[half] - mnew);
            float rs = 0.f;
            #pragma unroll
            for (int nt = 0; nt < 8; nt++) {
                s[nt][half * 2]     = __expf(s[nt][half * 2]     - mnew);
                s[nt][half * 2 + 1] = __expf(s[nt][half * 2 + 1] - mnew);
                rs += s[nt][half * 2] + s[nt][half * 2 + 1];
            }
            rs += __shfl_xor_sync(0xffffffffu, rs, 1);
            rs += __shfl_xor_sync(0xffffffffu, rs, 2);

            l_i[half] = l_i[half] * corr + rs;
            m_i[half] = mnew;
            #pragma unroll
            for (int nt = 0; nt < 8; nt++) {
                o[nt][half * 2]     *= corr;
                o[nt][half * 2 + 1] *= corr;
            }
        }

        // P -> smem as tf32 (warp-private rows)
        __syncwarp();
        #pragma unroll
        for (int nt = 0; nt < 8; nt++) {
            int cc = nt * 8 + tg * 2;
            Ps[(row_base + gid    ) * PS_P + cc    ] = f2tf32(s[nt][0]);
            Ps[(row_base + gid    ) * PS_P + cc + 1] = f2tf32(s[nt][1]);
            Ps[(row_base + gid + 8) * PS_P + cc    ] = f2tf32(s[nt][2]);
            Ps[(row_base + gid + 8) * PS_P + cc + 1] = f2tf32(s[nt][3]);
        }
        __syncwarp();

        // O += P @ V
        #pragma unroll
        for (int c8 = 0; c8 < 8; c8++) {
            int ks = c8 * 8;
            uint32_t a0 = Ps[(row_base + gid    ) * PS_P + ks + tg];
            uint32_t a1 = Ps[(row_base + gid + 8) * PS_P + ks + tg];
            uint32_t a2 = Ps[(row_base + gid    ) * PS_P + ks + tg + 4];
            uint32_t a3 = Ps[(row_base + gid + 8) * PS_P + ks + tg + 4];
            #pragma unroll
            for (int nt = 0; nt < 8; nt++) {
                uint32_t b0 = f2tf32(Vs[(ks + tg    ) * VS_P + nt * 8 + gid]);
                uint32_t b1 = f2tf32(Vs[(ks + tg + 4) * VS_P + nt * 8 + gid]);
                mma_tf32(o[nt], a0, a1, a2, a3, b0, b1);
            }
        }
        st ^= 1;
    }

    // Epilogue
    float inv0 = 1.0f / l_i[0];
    float inv1 = 1.0f / l_i[1];
    float* Ob = O + (size_t)b * SEQ * D_MODEL + h * D_K;
    int r0 = q0 + row_base + gid;
    #pragma unroll
    for (int nt = 0; nt < 8; nt++) {
        int col = nt * 8 + tg * 2;
        float2 t0 = { o[nt][0] * inv0, o[nt][1] * inv0 };
        *(float2*)&Ob[(size_t)r0 * D_MODEL + col] = t0;
        float2 t1 = { o[nt][2] * inv1, o[nt][3] * inv1 };
        *(float2*)&Ob[(size_t)(r0 + 8) * D_MODEL + col] = t1;
    }
}

// ---------------------------------------------------------------------------
// kernel_launch — inputs: q, k, v, w_q, b_q, w_k, b_k, w_v, b_v, w_o, b_o
// ---------------------------------------------------------------------------
extern "C" void kernel_launch(void* const* d_in, const int* in_sizes, int n_in,
                              void* d_out, int out_size)
{
    const float* q   = (const float*)d_in[0];
    const float* k   = (const float*)d_in[1];
    const float* v   = (const float*)d_in[2];
    const float* w_q = (const float*)d_in[3];
    const float* b_q = (const float*)d_in[4];
    const float* w_k = (const float*)d_in[5];
    const float* b_k = (const float*)d_in[6];
    const float* w_v = (const float*)d_in[7];
    const float* b_v = (const float*)d_in[8];
    const float* w_o = (const float*)d_in[9];
    const float* b_o = (const float*)d_in[10];
    float* out = (float*)d_out;

    float *gq, *gk, *gv, *go;
    cudaGetSymbolAddress((void**)&gq, g_Q);
    cudaGetSymbolAddress((void**)&gk, g_K);
    cudaGetSymbolAddress((void**)&gv, g_V);
    cudaGetSymbolAddress((void**)&go, g_O);

    cudaFuncSetAttribute(gemm_tf32, cudaFuncAttributeMaxDynamicSharedMemorySize, GEMM_SMEM);
    cudaFuncSetAttribute(attn_tf32, cudaFuncAttributeMaxDynamicSharedMemorySize, ATTN_SMEM);

    dim3 gemm_grid(D_MODEL / 128, M_ROWS / 128);  // (8, 32)
    gemm_tf32<<<gemm_grid, 256, GEMM_SMEM>>>(q, w_q, b_q, gq);
    gemm_tf32<<<gemm_grid, 256, GEMM_SMEM>>>(k, w_k, b_k, gk);
    gemm_tf32<<<gemm_grid, 256, GEMM_SMEM>>>(v, w_v, b_v, gv);

    dim3 attn_grid(SEQ / 128, N_HEADS, BATCH);    // (16, 16, 2)
    attn_tf32<<<attn_grid, 256, ATTN_SMEM>>>(gq, gk, gv, go);

    gemm_tf32<<<gemm_grid, 256, GEMM_SMEM>>>(go, w_o, b_o, out);
}

// round 4
// speedup vs baseline: 3.5722x; 1.0838x over previous
#include <cuda_runtime.h>
#include <cstdint>

#define D_MODEL 1024
#define N_HEADS 16
#define D_K     64
#define BATCH   2
#define SEQ     2048
#define M_ROWS  (BATCH * SEQ)   // 4096

// Scratch (allocation-free rule: __device__ globals). All tf32 payloads are
// stored as uint32 bit patterns.
__device__ uint32_t t_q [M_ROWS * D_MODEL];
__device__ uint32_t t_k [M_ROWS * D_MODEL];
__device__ uint32_t t_v [M_ROWS * D_MODEL];
__device__ uint32_t t_wq[D_MODEL * D_MODEL];
__device__ uint32_t t_wk[D_MODEL * D_MODEL];
__device__ uint32_t t_wv[D_MODEL * D_MODEL];
__device__ uint32_t t_wo[D_MODEL * D_MODEL];
__device__ uint32_t g_Q [M_ROWS * D_MODEL];   // projected Q, pre-scaled, tf32
__device__ uint32_t g_K [M_ROWS * D_MODEL];   // projected K, tf32
__device__ uint32_t g_V [M_ROWS * D_MODEL];   // projected V, tf32
__device__ uint32_t g_O [M_ROWS * D_MODEL];   // attention out, tf32

__device__ __forceinline__ uint32_t f2tf32(float x) {
    uint32_t r;
    asm("cvt.rna.tf32.f32 %0, %1;" : "=r"(r) : "f"(x));
    return r;
}

__device__ __forceinline__ void mma_tf32(float c[4],
                                         uint32_t a0, uint32_t a1, uint32_t a2, uint32_t a3,
                                         uint32_t b0, uint32_t b1) {
    asm volatile(
        "mma.sync.aligned.m16n8k8.row.col.f32.tf32.tf32.f32 "
        "{%0,%1,%2,%3}, {%4,%5,%6,%7}, {%8,%9}, {%0,%1,%2,%3};"
        : "+f"(c[0]), "+f"(c[1]), "+f"(c[2]), "+f"(c[3])
        : "r"(a0), "r"(a1), "r"(a2), "r"(a3), "r"(b0), "r"(b1));
}

__device__ __forceinline__ uint32_t smem_u32(const void* p) {
    return (uint32_t)__cvta_generic_to_shared(p);
}
__device__ __forceinline__ void cpasync16(uint32_t dst, const void* src) {
    asm volatile("cp.async.cg.shared.global [%0], [%1], 16;" :: "r"(dst), "l"(src));
}
__device__ __forceinline__ void cpasync_commit() {
    asm volatile("cp.async.commit_group;");
}
__device__ __forceinline__ void cpasync_wait_all() {
    asm volatile("cp.async.wait_group 0;");
}

// ---------------------------------------------------------------------------
// Pre-pass: fp32 -> tf32 bit pattern (vectorized). n4 = element count / 4.
// ---------------------------------------------------------------------------
__global__ __launch_bounds__(256)
void cvt_tf32_kernel(const float4* __restrict__ in, uint4* __restrict__ out, int n4)
{
    int idx = blockIdx.x * 256 + threadIdx.x;
    if (idx < n4) {
        float4 a = in[idx];
        uint4 u = { f2tf32(a.x), f2tf32(a.y), f2tf32(a.z), f2tf32(a.w) };
        out[idx] = u;
    }
}

// ---------------------------------------------------------------------------
// TF32 GEMM: C = alpha * (A @ W + bias). A, W are tf32 bit patterns.
// BM=BN=128, BK=32, 2-stage cp.async. 256 threads; warp tile 64x32.
// OUT_TF32: 1 -> store tf32 bits, 0 -> store fp32.
// ---------------------------------------------------------------------------
#define GA_P 36
#define GB_P 136
#define GEMM_STAGE_A (128 * GA_P)
#define GEMM_STAGE_B (32 * GB_P)
#define GEMM_SMEM ((2 * (GEMM_STAGE_A + GEMM_STAGE_B)) * 4)

template<int OUT_TF32>
__global__ __launch_bounds__(256)
void gemm_tf32(const uint32_t* __restrict__ A,
               const uint32_t* __restrict__ W,
               const float* __restrict__ bias,
               void* __restrict__ Cout,
               float alpha)
{
    extern __shared__ uint32_t sg[];
    uint32_t* Asm = sg;                        // [2][128][GA_P]
    uint32_t* Bsm = sg + 2 * GEMM_STAGE_A;     // [2][32][GB_P]

    const int tid  = threadIdx.x;
    const int lane = tid & 31;
    const int wid  = tid >> 5;
    const int gid  = lane >> 2;
    const int tg   = lane & 3;
    const int warp_m = wid & 1;
    const int warp_n = wid >> 1;
    const int m0 = blockIdx.y * 128;
    const int n0 = blockIdx.x * 128;

    float c[4][4][4];
    #pragma unroll
    for (int mt = 0; mt < 4; mt++)
        #pragma unroll
        for (int nt = 0; nt < 4; nt++)
            #pragma unroll
            for (int i = 0; i < 4; i++) c[mt][nt][i] = 0.f;

    // Prologue: stage 0
    #pragma unroll
    for (int i = 0; i < 4; i++) {
        int idx = tid + i * 256;
        int row = idx >> 3, kk = (idx & 7) * 4;
        cpasync16(smem_u32(&Asm[row * GA_P + kk]),
                  &A[(size_t)(m0 + row) * D_MODEL + kk]);
    }
    #pragma unroll
    for (int i = 0; i < 4; i++) {
        int idx = tid + i * 256;
        int kk = idx >> 5, col = (idx & 31) * 4;
        cpasync16(smem_u32(&Bsm[kk * GB_P + col]),
                  &W[(size_t)kk * D_MODEL + n0 + col]);
    }
    cpasync_commit();

    int st = 0;
    for (int k0 = 0; k0 < D_MODEL; k0 += 32) {
        cpasync_wait_all();
        __syncthreads();

        if (k0 + 32 < D_MODEL) {
            uint32_t* Ad = Asm + (st ^ 1) * GEMM_STAGE_A;
            uint32_t* Bd = Bsm + (st ^ 1) * GEMM_STAGE_B;
            #pragma unroll
            for (int i = 0; i < 4; i++) {
                int idx = tid + i * 256;
                int row = idx >> 3, kk = (idx & 7) * 4;
                cpasync16(smem_u32(&Ad[row * GA_P + kk]),
                          &A[(size_t)(m0 + row) * D_MODEL + k0 + 32 + kk]);
            }
            #pragma unroll
            for (int i = 0; i < 4; i++) {
                int idx = tid + i * 256;
                int kk = idx >> 5, col = (idx & 31) * 4;
                cpasync16(smem_u32(&Bd[kk * GB_P + col]),
                          &W[(size_t)(k0 + 32 + kk) * D_MODEL + n0 + col]);
            }
            cpasync_commit();
        }

        const uint32_t* As = Asm + st * GEMM_STAGE_A;
        const uint32_t* Bq = Bsm + st * GEMM_STAGE_B;

        #pragma unroll
        for (int ks = 0; ks < 32; ks += 8) {
            uint32_t af[4][4], bf[4][2];
            #pragma unroll
            for (int mt = 0; mt < 4; mt++) {
                int r = warp_m * 64 + mt * 16;
                af[mt][0] = As[(r + gid    ) * GA_P + ks + tg];
                af[mt][1] = As[(r + gid + 8) * GA_P + ks + tg];
                af[mt][2] = As[(r + gid    ) * GA_P + ks + tg + 4];
                af[mt][3] = As[(r + gid + 8) * GA_P + ks + tg + 4];
            }
            #pragma unroll
            for (int nt = 0; nt < 4; nt++) {
                int cb = warp_n * 32 + nt * 8;
                bf[nt][0] = Bq[(ks + tg    ) * GB_P + cb + gid];
                bf[nt][1] = Bq[(ks + tg + 4) * GB_P + cb + gid];
            }
            #pragma unroll
            for (int mt = 0; mt < 4; mt++)
                #pragma unroll
                for (int nt = 0; nt < 4; nt++)
                    mma_tf32(c[mt][nt], af[mt][0], af[mt][1], af[mt][2], af[mt][3],
                             bf[nt][0], bf[nt][1]);
        }
        st ^= 1;
    }

    #pragma unroll
    for (int mt = 0; mt < 4; mt++) {
        int r0 = m0 + warp_m * 64 + mt * 16 + gid;
        #pragma unroll
        for (int nt = 0; nt < 4; nt++) {
            int col = n0 + warp_n * 32 + nt * 8 + tg * 2;
            float2 bb = *(const float2*)&bias[col];
            float v00 = alpha * (c[mt][nt][0] + bb.x);
            float v01 = alpha * (c[mt][nt][1] + bb.y);
            float v10 = alpha * (c[mt][nt][2] + bb.x);
            float v11 = alpha * (c[mt][nt][3] + bb.y);
            if (OUT_TF32) {
                uint32_t* C = (uint32_t*)Cout;
                uint2 u0 = { f2tf32(v00), f2tf32(v01) };
                *(uint2*)&C[(size_t)r0 * D_MODEL + col] = u0;
                uint2 u1 = { f2tf32(v10), f2tf32(v11) };
                *(uint2*)&C[(size_t)(r0 + 8) * D_MODEL + col] = u1;
            } else {
                float* C = (float*)Cout;
                float2 o0 = { v00, v01 };
                *(float2*)&C[(size_t)r0 * D_MODEL + col] = o0;
                float2 o1 = { v10, v11 };
                *(float2*)&C[(size_t)(r0 + 8) * D_MODEL + col] = o1;
            }
        }
    }
}

// ---------------------------------------------------------------------------
// TF32 flash attention. CTA = 128 q rows x one (b,h). 8 warps x 16 rows.
// Q pre-scaled tf32 in registers; K/V pre-converted tf32 via 2-stage cp.async.
// P via smem (tf32). Output written as tf32 bits to g_O.
// Dynamic smem: (2*64*68 + 2*64*72 + 128*68) * 4 = 106496 B.
// ---------------------------------------------------------------------------
#define KS_P 68
#define VS_P 72
#define PS_P 68
#define K_STAGE (64 * KS_P)
#define V_STAGE (64 * VS_P)
#define ATTN_SMEM ((2 * K_STAGE + 2 * V_STAGE + 128 * PS_P) * 4)

__global__ __launch_bounds__(256)
void attn_tf32(const uint32_t* __restrict__ Q,
               const uint32_t* __restrict__ K,
               const uint32_t* __restrict__ V,
               uint32_t* __restrict__ O)
{
    extern __shared__ uint32_t sa[];
    uint32_t* Kbuf = sa;                         // [2][64][KS_P] tf32
    uint32_t* Vbuf = sa + 2 * K_STAGE;           // [2][64][VS_P] tf32
    uint32_t* Ps   = sa + 2 * K_STAGE + 2 * V_STAGE;  // [128][PS_P] tf32

    const int tid  = threadIdx.x;
    const int lane = tid & 31;
    const int wid  = tid >> 5;
    const int gid  = lane >> 2;
    const int tg   = lane & 3;
    const int row_base = wid * 16;

    const int q0 = blockIdx.x * 128;
    const int h  = blockIdx.y;
    const int b  = blockIdx.z;

    const uint32_t* Qb = Q + (size_t)b * SEQ * D_MODEL + h * D_K;
    const uint32_t* Kb = K + (size_t)b * SEQ * D_MODEL + h * D_K;
    const uint32_t* Vb = V + (size_t)b * SEQ * D_MODEL + h * D_K;

    // Q fragments (already scaled by 1/8 and tf32-converted by the projection)
    uint32_t qf[8][4];
    {
        const uint32_t* qr0 = Qb + (size_t)(q0 + row_base + gid) * D_MODEL;
        const uint32_t* qr1 = qr0 + (size_t)8 * D_MODEL;
        #pragma unroll
        for (int c8 = 0; c8 < 8; c8++) {
            qf[c8][0] = qr0[c8 * 8 + tg    ];
            qf[c8][1] = qr1[c8 * 8 + tg    ];
            qf[c8][2] = qr0[c8 * 8 + tg + 4];
            qf[c8][3] = qr1[c8 * 8 + tg + 4];
        }
    }

    // Prologue: stage 0 K/V
    #pragma unroll
    for (int i = 0; i < 4; i++) {
        int idx = tid + i * 256;
        int r = idx >> 4, c4 = (idx & 15) * 4;
        cpasync16(smem_u32(&Kbuf[r * KS_P + c4]), &Kb[(size_t)r * D_MODEL + c4]);
        cpasync16(smem_u32(&Vbuf[r * VS_P + c4]), &Vb[(size_t)r * D_MODEL + c4]);
    }
    cpasync_commit();

    float o[8][4];
    #pragma unroll
    for (int nt = 0; nt < 8; nt++)
        #pragma unroll
        for (int i = 0; i < 4; i++) o[nt][i] = 0.f;
    float m_i[2] = { -1e30f, -1e30f };
    float l_i[2] = { 0.f, 0.f };

    int st = 0;
    for (int kt = 0; kt < SEQ; kt += 64) {
        cpasync_wait_all();
        __syncthreads();

        if (kt + 64 < SEQ) {
            uint32_t* Kd = Kbuf + (st ^ 1) * K_STAGE;
            uint32_t* Vd = Vbuf + (st ^ 1) * V_STAGE;
            #pragma unroll
            for (int i = 0; i < 4; i++) {
                int idx = tid + i * 256;
                int r = idx >> 4, c4 = (idx & 15) * 4;
                cpasync16(smem_u32(&Kd[r * KS_P + c4]),
                          &Kb[(size_t)(kt + 64 + r) * D_MODEL + c4]);
                cpasync16(smem_u32(&Vd[r * VS_P + c4]),
                          &Vb[(size_t)(kt + 64 + r) * D_MODEL + c4]);
            }
            cpasync_commit();
        }

        const uint32_t* Ks = Kbuf + st * K_STAGE;
        const uint32_t* Vs = Vbuf + st * V_STAGE;

        // S = Q @ K^T
        float s[8][4];
        #pragma unroll
        for (int nt = 0; nt < 8; nt++)
            #pragma unroll
            for (int i = 0; i < 4; i++) s[nt][i] = 0.f;

        #pragma unroll
        for (int c8 = 0; c8 < 8; c8++) {
            int ks = c8 * 8;
            #pragma unroll
            for (int nt = 0; nt < 8; nt++) {
                uint32_t b0 = Ks[(nt * 8 + gid) * KS_P + ks + tg];
                uint32_t b1 = Ks[(nt * 8 + gid) * KS_P + ks + tg + 4];
                mma_tf32(s[nt], qf[c8][0], qf[c8][1], qf[c8][2], qf[c8][3], b0, b1);
            }
        }

        // Online softmax
        #pragma unroll
        for (int half = 0; half < 2; half++) {
            float mx = -1e30f;
            #pragma unroll
            for (int nt = 0; nt < 8; nt++)
                mx = fmaxf(mx, fmaxf(s[nt][half * 2], s[nt][half * 2 + 1]));
            mx = fmaxf(mx, __shfl_xor_sync(0xffffffffu, mx, 1));
            mx = fmaxf(mx, __shfl_xor_sync(0xffffffffu, mx, 2));

            float mnew = fmaxf(m_i[half], mx);
            float corr = __expf(m_i[half] - mnew);
            float rs = 0.f;
            #pragma unroll
            for (int nt = 0; nt < 8; nt++) {
                s[nt][half * 2]     = __expf(s[nt][half * 2]     - mnew);
                s[nt][half * 2 + 1] = __expf(s[nt][half * 2 + 1] - mnew);
                rs += s[nt][half * 2] + s[nt][half * 2 + 1];
            }
            rs += __shfl_xor_sync(0xffffffffu, rs, 1);
            rs += __shfl_xor_sync(0xffffffffu, rs, 2);

            l_i[half] = l_i[half] * corr + rs;
            m_i[half] = mnew;
            #pragma unroll
            for (int nt = 0; nt < 8; nt++) {
                o[nt][half * 2]     *= corr;
                o[nt][half * 2 + 1] *= corr;
            }
        }

        // P -> smem tf32 (warp-private rows)
        __syncwarp();
        #pragma unroll
        for (int nt = 0; nt < 8; nt++) {
            int cc = nt * 8 + tg * 2;
            Ps[(row_base + gid    ) * PS_P + cc    ] = f2tf32(s[nt][0]);
            Ps[(row_base + gid    ) * PS_P + cc + 1] = f2tf32(s[nt][1]);
            Ps[(row_base + gid + 8) * PS_P + cc    ] = f2tf32(s[nt][2]);
            Ps[(row_base + gid + 8) * PS_P + cc + 1] = f2tf32(s[nt][3]);
        }
        __syncwarp();

        // O += P @ V
        #pragma unroll
        for (int c8 = 0; c8 < 8; c8++) {
            int ks = c8 * 8;
            uint32_t a0 = Ps[(row_base + gid    ) * PS_P + ks + tg];
            uint32_t a1 = Ps[(row_base + gid + 8) * PS_P + ks + tg];
            uint32_t a2 = Ps[(row_base + gid    ) * PS_P + ks + tg + 4];
            uint32_t a3 = Ps[(row_base + gid + 8) * PS_P + ks + tg + 4];
            #pragma unroll
            for (int nt = 0; nt < 8; nt++) {
                uint32_t b0 = Vs[(ks + tg    ) * VS_P + nt * 8 + gid];
                uint32_t b1 = Vs[(ks + tg + 4) * VS_P + nt * 8 + gid];
                mma_tf32(o[nt], a0, a1, a2, a3, b0, b1);
            }
        }
        st ^= 1;
    }

    // Epilogue: normalize, write tf32 bits for the O projection
    float inv0 = 1.0f / l_i[0];
    float inv1 = 1.0f / l_i[1];
    uint32_t* Ob = O + (size_t)b * SEQ * D_MODEL + h * D_K;
    int r0 = q0 + row_base + gid;
    #pragma unroll
    for (int nt = 0; nt < 8; nt++) {
        int col = nt * 8 + tg * 2;
        uint2 t0 = { f2tf32(o[nt][0] * inv0), f2tf32(o[nt][1] * inv0) };
        *(uint2*)&Ob[(size_t)r0 * D_MODEL + col] = t0;
        uint2 t1 = { f2tf32(o[nt][2] * inv1), f2tf32(o[nt][3] * inv1) };
        *(uint2*)&Ob[(size_t)(r0 + 8) * D_MODEL + col] = t1;
    }
}

// ---------------------------------------------------------------------------
// kernel_launch — inputs: q, k, v, w_q, b_q, w_k, b_k, w_v, b_v, w_o, b_o
// ---------------------------------------------------------------------------
extern "C" void kernel_launch(void* const* d_in, const int* in_sizes, int n_in,
                              void* d_out, int out_size)
{
    const float* q   = (const float*)d_in[0];
    const float* k   = (const float*)d_in[1];
    const float* v   = (const float*)d_in[2];
    const float* w_q = (const float*)d_in[3];
    const float* b_q = (const float*)d_in[4];
    const float* w_k = (const float*)d_in[5];
    const float* b_k = (const float*)d_in[6];
    const float* w_v = (const float*)d_in[7];
    const float* b_v = (const float*)d_in[8];
    const float* w_o = (const float*)d_in[9];
    const float* b_o = (const float*)d_in[10];
    float* out = (float*)d_out;

    uint32_t *tq, *tk, *tv, *twq, *twk, *twv, *two, *gq, *gk, *gv, *go;
    cudaGetSymbolAddress((void**)&tq,  t_q);
    cudaGetSymbolAddress((void**)&tk,  t_k);
    cudaGetSymbolAddress((void**)&tv,  t_v);
    cudaGetSymbolAddress((void**)&twq, t_wq);
    cudaGetSymbolAddress((void**)&twk, t_wk);
    cudaGetSymbolAddress((void**)&twv, t_wv);
    cudaGetSymbolAddress((void**)&two, t_wo);
    cudaGetSymbolAddress((void**)&gq,  g_Q);
    cudaGetSymbolAddress((void**)&gk,  g_K);
    cudaGetSymbolAddress((void**)&gv,  g_V);
    cudaGetSymbolAddress((void**)&go,  g_O);

    cudaFuncSetAttribute(gemm_tf32<0>, cudaFuncAttributeMaxDynamicSharedMemorySize, GEMM_SMEM);
    cudaFuncSetAttribute(gemm_tf32<1>, cudaFuncAttributeMaxDynamicSharedMemorySize, GEMM_SMEM);
    cudaFuncSetAttribute(attn_tf32,    cudaFuncAttributeMaxDynamicSharedMemorySize, ATTN_SMEM);

    // Pre-pass: convert activations + weights to tf32 bit patterns
    const int n4_act = M_ROWS * D_MODEL / 4;      // 1048576
    const int n4_w   = D_MODEL * D_MODEL / 4;     // 262144
    cvt_tf32_kernel<<<n4_act / 256, 256>>>((const float4*)q,   (uint4*)tq,  n4_act);
    cvt_tf32_kernel<<<n4_act / 256, 256>>>((const float4*)k,   (uint4*)tk,  n4_act);
    cvt_tf32_kernel<<<n4_act / 256, 256>>>((const float4*)v,   (uint4*)tv,  n4_act);
    cvt_tf32_kernel<<<n4_w   / 256, 256>>>((const float4*)w_q, (uint4*)twq, n4_w);
    cvt_tf32_kernel<<<n4_w   / 256, 256>>>((const float4*)w_k, (uint4*)twk, n4_w);
    cvt_tf32_kernel<<<n4_w   / 256, 256>>>((const float4*)w_v, (uint4*)twv, n4_w);
    cvt_tf32_kernel<<<n4_w   / 256, 256>>>((const float4*)w_o, (uint4*)two, n4_w);

    dim3 gemm_grid(D_MODEL / 128, M_ROWS / 128);  // (8, 32)
    // Q projection: fold the 1/sqrt(d_k)=0.125 attention scale into alpha
    gemm_tf32<1><<<gemm_grid, 256, GEMM_SMEM>>>(tq, twq, b_q, gq, 0.125f);
    gemm_tf32<1><<<gemm_grid, 256, GEMM_SMEM>>>(tk, twk, b_k, gk, 1.0f);
    gemm_tf32<1><<<gemm_grid, 256, GEMM_SMEM>>>(tv, twv, b_v, gv, 1.0f);

    dim3 attn_grid(SEQ / 128, N_HEADS, BATCH);    // (16, 16, 2)
    attn_tf32<<<attn_grid, 256, ATTN_SMEM>>>(gq, gk, gv, go);

    gemm_tf32<0><<<gemm_grid, 256, GEMM_SMEM>>>(go, two, b_o, out, 1.0f);
}